// round 16
// baseline (speedup 1.0000x reference)
#include <cuda_runtime.h>

#define NRAD  16
#define NL    2
#define NOUT  144            // 16*(1 + 2*4)
#define L35   35
#define K48   48             // k padded: 35 real + 13 zero
#define NKGP  6              // 6 chunks of 8 k per thread
#define HALFT 96             // threads per atom: 16 j x 6 kgp = 3 warps
#define BLOCK 192            // 2 atoms per block -> 6 warps
#define MAXE   100000
#define MAXNAT 4096

__device__ int    g_segstart[MAXNAT + 1];
__device__ float4 g_gT[12 * MAXE];      // plane p: k = p*4 .. p*4+3, [p][e]

typedef unsigned long long ull;

__device__ __forceinline__ ull pack2(float x, float y) {
    ull r; asm("mov.b64 %0, {%1, %2};" : "=l"(r) : "f"(x), "f"(y)); return r;
}
__device__ __forceinline__ ull dup2(float x) {
    ull r; asm("mov.b64 %0, {%1, %1};" : "=l"(r) : "f"(x)); return r;
}
__device__ __forceinline__ void unpack2(ull p, float& x, float& y) {
    asm("mov.b64 {%0, %1}, %2;" : "=f"(x), "=f"(y) : "l"(p));
}
__device__ __forceinline__ void fma2(ull& d, ull a, ull b) {
    asm("fma.rn.f32x2 %0, %1, %2, %0;" : "+l"(d) : "l"(a), "l"(b));
}

// lambda exponent per k (48 entries, pads 0 -> lam value forced 0 anyway)
__constant__ int c_S[K48] = {0, 1,1,1, 2,2,2,2,2,2,
                             3,3,3,3,3,3,3,3,3,3,
                             4,4,4,4,4,4,4,4,4,4,4,4,4,4,4,
                             0,0,0,0,0,0,0,0,0,0,0,0,0};

// Compile-time monomial tables, 48 slots (35 real, 13 zero-pad)
template<int P>
__device__ __forceinline__ float4 mono4(float x, float y, float z)
{
    constexpr int LX[K48] = {0, 0,0,1, 0,0,0,1,1,2,
                             0,0,0,0,1,1,1,2,2,3,
                             0,0,0,0,0,1,1,1,1,2,2,2,3,3,4,
                             0,0,0,0,0,0,0,0,0,0,0,0,0};
    constexpr int LY[K48] = {0, 0,1,0, 0,1,2,0,1,0,
                             0,1,2,3,0,1,2,0,1,0,
                             0,1,2,3,4,0,1,2,3,0,1,2,0,1,0,
                             0,0,0,0,0,0,0,0,0,0,0,0,0};
    constexpr int LZ[K48] = {0, 1,0,0, 2,1,0,1,0,0,
                             3,2,1,0,2,1,0,1,0,0,
                             4,3,2,1,0,3,2,1,0,2,1,0,1,0,0,
                             0,0,0,0,0,0,0,0,0,0,0,0,0};
    constexpr float FN[K48] = {1.f, 1.f,1.f,1.f,
                               1.f,2.f,1.f,2.f,2.f,1.f,
                               1.f,3.f,3.f,1.f,3.f,6.f,3.f,3.f,3.f,1.f,
                               1.f,4.f,6.f,4.f,1.f,4.f,12.f,12.f,4.f,
                               6.f,12.f,6.f,4.f,4.f,1.f,
                               0.f,0.f,0.f,0.f,0.f,0.f,0.f,0.f,0.f,0.f,0.f,0.f,0.f};
    float px[5], py[5], pz[5];
    px[0]=1.f; px[1]=x; px[2]=x*x; px[3]=px[2]*x; px[4]=px[2]*px[2];
    py[0]=1.f; py[1]=y; py[2]=y*y; py[3]=py[2]*y; py[4]=py[2]*py[2];
    pz[0]=1.f; pz[1]=z; pz[2]=z*z; pz[3]=pz[2]*z; pz[4]=pz[2]*pz[2];
    float4 m;
    m.x = FN[P*4+0] * px[LX[P*4+0]] * py[LY[P*4+0]] * pz[LZ[P*4+0]];
    m.y = FN[P*4+1] * px[LX[P*4+1]] * py[LY[P*4+1]] * pz[LZ[P*4+1]];
    m.z = FN[P*4+2] * px[LX[P*4+2]] * py[LY[P*4+2]] * pz[LZ[P*4+2]];
    m.w = FN[P*4+3] * px[LX[P*4+3]] * py[LY[P*4+3]] * pz[LZ[P*4+3]];
    return m;
}

// Prep: 2D grid (E/256, 12). One thread per (edge, 4-k plane).
__global__ __launch_bounds__(256)
void prep_kernel(const float* __restrict__ rij, const int* __restrict__ fidx,
                 int E, int nat)
{
    const int e = blockIdx.x * 256 + threadIdx.x;
    const int p = blockIdx.y;
    if (e >= E) return;

    if (p == 0) {
        int cur  = __ldg(&fidx[e]);
        int prev = (e == 0) ? -1 : __ldg(&fidx[e - 1]);
        for (int a = prev + 1; a <= cur; a++) g_segstart[a] = e;
        if (e == E - 1)
            for (int a = cur + 1; a <= nat; a++) g_segstart[a] = E;
    }

    float x = __ldg(&rij[e*3+0]);
    float y = __ldg(&rij[e*3+1]);
    float z = __ldg(&rij[e*3+2]);

    float4 m;
    switch (p) {
        case 0:  m = mono4<0>(x,y,z); break;
        case 1:  m = mono4<1>(x,y,z); break;
        case 2:  m = mono4<2>(x,y,z); break;
        case 3:  m = mono4<3>(x,y,z); break;
        case 4:  m = mono4<4>(x,y,z); break;
        case 5:  m = mono4<5>(x,y,z); break;
        case 6:  m = mono4<6>(x,y,z); break;
        case 7:  m = mono4<7>(x,y,z); break;
        case 8:  m = mono4<8>(x,y,z); break;
        default: m = make_float4(0.f, 0.f, 0.f, 0.f); break;   // pure pad planes
    }
    g_gT[p * MAXE + e] = m;
}

__global__ __launch_bounds__(BLOCK, 4)
void mbp_main(const float* __restrict__ radial,   // [E,16,5]
              const float* __restrict__ lamw,     // [NL]
              float* __restrict__ out,            // [nat, NOUT]
              int nat)
{
    __shared__ float s_lam[NL][K48];
    __shared__ float s_part[2][NKGP][NRAD][8];

    const int tid  = threadIdx.x;
    const int half = (tid >= HALFT) ? 1 : 0;
    const int t    = tid - half * HALFT;
    const int j    = t & 15;        // 0..15 radial index
    const int kgp  = t >> 4;        // 0..5  angular chunk (8 k each)
    const int a    = blockIdx.x * 2 + half;

    if (tid < NL * K48) {
        int l = (tid >= K48) ? 1 : 0;
        int k = tid - l * K48;
        float p = 0.f;
        if (k < L35) {
            float b = lamw[l];
            int   s = c_S[k];
            p = 1.f;                       // exact integer power (b may be < 0)
            for (int i = 0; i < s; i++) p *= b;
        }
        s_lam[l][k] = p;
    }
    const int start = (a < nat) ? g_segstart[a]     : 0;
    const int end   = (a < nat) ? g_segstart[a + 1] : 0;
    __syncthreads();

    // acc[p][c]: k-pair (kgp*8 + 2p, +2p+1), radial channel c
    ull acc[4][4];
    #pragma unroll
    for (int p = 0; p < 4; p++)
        #pragma unroll
        for (int c = 0; c < 4; c++) acc[p][c] = 0ull;
    float accR = 0.f;               // two-body channel (kgp==0 only)

    const float*  rp  = radial + (size_t)start * 80 + j * 5;
    const float4* gpA = g_gT + (size_t)(2*kgp)     * MAXE + start;
    const float4* gpB = g_gT + (size_t)(2*kgp + 1) * MAXE + start;

    #pragma unroll 8
    for (int e = start; e < end; e++) {
        float4 ga = *gpA++;
        float4 gb = *gpB++;
        float r0 = rp[0], r1 = rp[1], r2 = rp[2], r3 = rp[3];
        if (kgp == 0) accR += rp[4];
        rp += 80;
        ull gA0 = pack2(ga.x, ga.y), gA1 = pack2(ga.z, ga.w);
        ull gB0 = pack2(gb.x, gb.y), gB1 = pack2(gb.z, gb.w);
        ull d0 = dup2(r0), d1 = dup2(r1), d2 = dup2(r2), d3 = dup2(r3);
        fma2(acc[0][0], gA0, d0);  fma2(acc[0][1], gA0, d1);
        fma2(acc[0][2], gA0, d2);  fma2(acc[0][3], gA0, d3);
        fma2(acc[1][0], gA1, d0);  fma2(acc[1][1], gA1, d1);
        fma2(acc[1][2], gA1, d2);  fma2(acc[1][3], gA1, d3);
        fma2(acc[2][0], gB0, d0);  fma2(acc[2][1], gB0, d1);
        fma2(acc[2][2], gB0, d2);  fma2(acc[2][3], gB0, d3);
        fma2(acc[3][0], gB1, d0);  fma2(acc[3][1], gB1, d1);
        fma2(acc[3][2], gB1, d2);  fma2(acc[3][3], gB1, d3);
    }

    // per-thread lambda contraction over this thread's 8 k-values
    {
        float po[4][2] = {{0,0},{0,0},{0,0},{0,0}};   // [c][l]
        #pragma unroll
        for (int p = 0; p < 4; p++) {
            float l0a = s_lam[0][kgp*8 + 2*p],     l1a = s_lam[1][kgp*8 + 2*p];
            float l0b = s_lam[0][kgp*8 + 2*p + 1], l1b = s_lam[1][kgp*8 + 2*p + 1];
            #pragma unroll
            for (int c = 0; c < 4; c++) {
                float u, v; unpack2(acc[p][c], u, v);
                float su = u*u, sv = v*v;
                po[c][0] = fmaf(su, l0a, fmaf(sv, l0b, po[c][0]));
                po[c][1] = fmaf(su, l1a, fmaf(sv, l1b, po[c][1]));
            }
        }
        #pragma unroll
        for (int c = 0; c < 4; c++) {
            s_part[half][kgp][j][c*2 + 0] = po[c][0];
            s_part[half][kgp][j][c*2 + 1] = po[c][1];
        }
    }
    if (kgp == 0 && a < nat) out[(size_t)a * NOUT + j] = accR;
    __syncthreads();

    // reduce over kgp chunks: 256 outputs = 2 atoms x (j2, c, l)
    for (int idx = tid; idx < 256; idx += BLOCK) {
        int h2  = idx >> 7;          // atom half
        int low = idx & 127;
        int co  = low & 7;           // c*2 + l
        int j2  = low >> 3;          // 0..15
        int ao  = blockIdx.x * 2 + h2;
        if (ao < nat) {
            float sum = 0.f;
            #pragma unroll
            for (int k = 0; k < NKGP; k++) sum += s_part[h2][k][j2][co];
            int c = co >> 1, l = co & 1;
            float scale = __int_as_float(0x3F800000 - (c << 23));   // 2^-c
            out[(size_t)ao * NOUT + NRAD + c*(NRAD*NL) + j2*NL + l] = sum * scale;
        }
    }
}

extern "C" void kernel_launch(void* const* d_in, const int* in_sizes, int n_in,
                              void* d_out, int out_size)
{
    const float* rij    = (const float*)d_in[0];   // [E,3]
    const float* radial = (const float*)d_in[1];   // [E,16,5]
    const float* lamw   = (const float*)d_in[2];   // [2]
    const int*   fidx   = (const int*)  d_in[4];   // [E] sorted

    const int E   = in_sizes[0] / 3;
    const int nat = out_size / NOUT;

    dim3 pgrid((E + 255) / 256, 12);
    prep_kernel<<<pgrid, 256>>>(rij, fidx, E, nat);
    mbp_main  <<<(nat + 1) / 2, BLOCK>>>(radial, lamw, (float*)d_out, nat);
}